// round 4
// baseline (speedup 1.0000x reference)
#include <cuda_runtime.h>
#include <cuda_bf16.h>
#include <math.h>

// ---------------------------------------------------------------------------
// Problem constants
//   D=384, NH=8, HD=48, KN=10, L=6
//   B=64, H=14 (query tokens per batch), NNODES=8192
//   Sequences: 640 (= B*KN), tokens per seq: 14  -> M = 8960 rows of dim 384
// ---------------------------------------------------------------------------
#define Dm      384
#define NHEAD   8
#define HDIM    48
#define KNN     10
#define NLAYER  6
#define BATCH   64
#define HTOK    14
#define NNODES  8192
#define MTOK    8960          // 640 * 14
#define EPSLN   1e-5f

// ---------------------------------------------------------------------------
// Device scratch (allocation-free: __device__ globals)
// ---------------------------------------------------------------------------
__device__ float g_sim [BATCH * HTOK * NNODES];   // 28 MB
__device__ int   g_idx [BATCH * HTOK * KNN];
__device__ float g_x   [MTOK * Dm];
__device__ float g_mem [MTOK * Dm];
__device__ float g_h   [MTOK * Dm];
__device__ float g_q   [MTOK * Dm];
__device__ float g_o   [MTOK * Dm];
__device__ float g_qkv [MTOK * 3 * Dm];
__device__ float g_kv  [MTOK * 2 * Dm];
__device__ float g_ff  [MTOK * 4 * Dm];

// ---------------------------------------------------------------------------
// 1) sim[b,h,n] = dot(qt[b,h,:], nd[b,n,:])
//    grid (32, 64), 256 threads. Warp per node, 32 nodes per warp.
// ---------------------------------------------------------------------------
__global__ void sim_kernel(const float* __restrict__ qt,
                           const float* __restrict__ nd,
                           float* __restrict__ sim)
{
    int b = blockIdx.y;
    __shared__ float qts[HTOK * Dm];   // 21.5 KB
    for (int i = threadIdx.x; i < HTOK * Dm; i += blockDim.x)
        qts[i] = qt[(size_t)b * HTOK * Dm + i];
    __syncthreads();

    int warp = threadIdx.x >> 5, lane = threadIdx.x & 31;
    int node0 = blockIdx.x * 256 + warp * 32;

    for (int it = 0; it < 32; ++it) {
        int node = node0 + it;
        const float* row = nd + ((size_t)b * NNODES + node) * Dm;
        float v[12];
        #pragma unroll
        for (int j = 0; j < 12; ++j) v[j] = row[lane + 32 * j];

        #pragma unroll
        for (int h = 0; h < HTOK; ++h) {
            float p = 0.f;
            #pragma unroll
            for (int j = 0; j < 12; ++j) p += v[j] * qts[h * Dm + lane + 32 * j];
            #pragma unroll
            for (int o = 16; o > 0; o >>= 1) p += __shfl_xor_sync(0xffffffffu, p, o);
            if (lane == 0)
                sim[((size_t)(b * HTOK + h)) * NNODES + node] = p;
        }
    }
}

// ---------------------------------------------------------------------------
// 2) top-10 per (b,h) row of 8192, sorted descending, ties -> lowest index
//    grid 896 blocks of 256 threads.
// ---------------------------------------------------------------------------
__global__ void topk_kernel(const float* __restrict__ sim, int* __restrict__ idx)
{
    __shared__ float vals[NNODES];     // 32 KB
    __shared__ float rv[256];
    __shared__ int   ri[256];
    int row = blockIdx.x;
    const float* s = sim + (size_t)row * NNODES;
    for (int i = threadIdx.x; i < NNODES; i += 256) vals[i] = s[i];
    __syncthreads();

    for (int t = 0; t < KNN; ++t) {
        float bv = -INFINITY; int bi = 0;
        for (int i = threadIdx.x; i < NNODES; i += 256) {
            float v = vals[i];
            if (v > bv) { bv = v; bi = i; }      // ascending scan -> lowest idx kept on tie
        }
        rv[threadIdx.x] = bv; ri[threadIdx.x] = bi;
        __syncthreads();
        for (int s2 = 128; s2 > 0; s2 >>= 1) {
            if (threadIdx.x < s2) {
                float ov = rv[threadIdx.x + s2]; int oi = ri[threadIdx.x + s2];
                if (ov > rv[threadIdx.x] ||
                    (ov == rv[threadIdx.x] && oi < ri[threadIdx.x])) {
                    rv[threadIdx.x] = ov; ri[threadIdx.x] = oi;
                }
            }
            __syncthreads();
        }
        if (threadIdx.x == 0) { idx[row * KNN + t] = ri[0]; vals[ri[0]] = -INFINITY; }
        __syncthreads();
    }
}

// ---------------------------------------------------------------------------
// 3) build x (broadcast qt) and mem (gathered nodes)
//    row = (b*10 + k)*14 + h ; grid 8960 blocks, 128 threads
// ---------------------------------------------------------------------------
__global__ void gather_kernel(const float* __restrict__ qt,
                              const float* __restrict__ nd,
                              const int*   __restrict__ idx,
                              float* __restrict__ x, float* __restrict__ mem)
{
    int row = blockIdx.x;
    int b = row / (KNN * HTOK);
    int k = (row / HTOK) % KNN;
    int h = row % HTOK;
    const float4* sx = (const float4*)(qt + (size_t)(b * HTOK + h) * Dm);
    int node = idx[(b * HTOK + h) * KNN + k];
    const float4* sm = (const float4*)(nd + ((size_t)b * NNODES + node) * Dm);
    float4* dx = (float4*)(x   + (size_t)row * Dm);
    float4* dm = (float4*)(mem + (size_t)row * Dm);
    for (int i = threadIdx.x; i < Dm / 4; i += blockDim.x) { dx[i] = sx[i]; dm[i] = sm[i]; }
}

// ---------------------------------------------------------------------------
// 4) LayerNorm: warp per row (384 = 32 lanes * 12), optional second output
//    grid 1120 blocks of 256 threads (8 warps)
// ---------------------------------------------------------------------------
__global__ void ln_kernel(const float* __restrict__ in,
                          float* __restrict__ out, float* __restrict__ out2,
                          const float* __restrict__ w, const float* __restrict__ bias)
{
    int warp = threadIdx.x >> 5, lane = threadIdx.x & 31;
    int row = blockIdx.x * (blockDim.x >> 5) + warp;
    if (row >= MTOK) return;
    const float* p = in + (size_t)row * Dm;
    float v[12];
    float s = 0.f;
    #pragma unroll
    for (int j = 0; j < 12; ++j) { v[j] = p[lane + 32 * j]; s += v[j]; }
    #pragma unroll
    for (int o = 16; o > 0; o >>= 1) s += __shfl_xor_sync(0xffffffffu, s, o);
    float mu = s * (1.f / Dm);
    float q = 0.f;
    #pragma unroll
    for (int j = 0; j < 12; ++j) { float d = v[j] - mu; q += d * d; }
    #pragma unroll
    for (int o = 16; o > 0; o >>= 1) q += __shfl_xor_sync(0xffffffffu, q, o);
    float inv = rsqrtf(q * (1.f / Dm) + EPSLN);
    float* po = out + (size_t)row * Dm;
    #pragma unroll
    for (int j = 0; j < 12; ++j) {
        int c = lane + 32 * j;
        float r = (v[j] - mu) * inv * w[c] + bias[c];
        po[c] = r;
        if (out2) out2[(size_t)row * Dm + c] = r;
    }
}

// ---------------------------------------------------------------------------
// 5) GEMM: C[m,n] = sum_k A[m,k] * W[n,k] + bias[n]   (both row-major, K inner)
//    EPI: 0 = store, 1 = gelu(store), 2 = C[m,n] += result (residual)
//    64x64x16 tile, 256 threads, 4x4 microtile. Requires M%64==0, N%64==0, K%16==0.
// ---------------------------------------------------------------------------
__device__ __forceinline__ float gelu_exact(float x)
{
    return 0.5f * x * (1.0f + erff(x * 0.70710678118654752f));
}

template <int EPI>
__global__ void gemm_kernel(const float* __restrict__ A,
                            const float* __restrict__ W,
                            const float* __restrict__ bias,
                            float* __restrict__ C,
                            int M, int N, int K)
{
    __shared__ __align__(16) float As[16][68];
    __shared__ __align__(16) float Bs[16][68];

    int m0 = blockIdx.y * 64, n0 = blockIdx.x * 64;
    int tid = threadIdx.x;
    int lrow = tid >> 2;            // 0..63
    int lk   = (tid & 3) * 4;       // 0,4,8,12
    int tx = tid & 15, ty = tid >> 4;

    const float* Ap = A + (size_t)(m0 + lrow) * K + lk;
    const float* Wp = W + (size_t)(n0 + lrow) * K + lk;

    float acc[4][4];
    #pragma unroll
    for (int i = 0; i < 4; ++i)
        #pragma unroll
        for (int j = 0; j < 4; ++j) acc[i][j] = 0.f;

    for (int k0 = 0; k0 < K; k0 += 16) {
        float4 av = *(const float4*)(Ap + k0);
        float4 wv = *(const float4*)(Wp + k0);
        __syncthreads();
        As[lk + 0][lrow] = av.x; As[lk + 1][lrow] = av.y;
        As[lk + 2][lrow] = av.z; As[lk + 3][lrow] = av.w;
        Bs[lk + 0][lrow] = wv.x; Bs[lk + 1][lrow] = wv.y;
        Bs[lk + 2][lrow] = wv.z; Bs[lk + 3][lrow] = wv.w;
        __syncthreads();
        #pragma unroll
        for (int kk = 0; kk < 16; ++kk) {
            float4 af = *(const float4*)&As[kk][ty * 4];
            float4 bf = *(const float4*)&Bs[kk][tx * 4];
            float a4[4] = {af.x, af.y, af.z, af.w};
            float b4[4] = {bf.x, bf.y, bf.z, bf.w};
            #pragma unroll
            for (int i = 0; i < 4; ++i)
                #pragma unroll
                for (int j = 0; j < 4; ++j) acc[i][j] += a4[i] * b4[j];
        }
    }

    float4 bv = *(const float4*)(bias + n0 + tx * 4);
    float b4[4] = {bv.x, bv.y, bv.z, bv.w};
    #pragma unroll
    for (int i = 0; i < 4; ++i) {
        int m = m0 + ty * 4 + i;
        float4* cp = (float4*)(C + (size_t)m * N + n0 + tx * 4);
        float r[4];
        #pragma unroll
        for (int j = 0; j < 4; ++j) r[j] = acc[i][j] + b4[j];
        if (EPI == 1) {
            #pragma unroll
            for (int j = 0; j < 4; ++j) r[j] = gelu_exact(r[j]);
        }
        if (EPI == 2) {
            float4 old = *cp;
            r[0] += old.x; r[1] += old.y; r[2] += old.z; r[3] += old.w;
        }
        float4 rv4 = make_float4(r[0], r[1], r[2], r[3]);
        *cp = rv4;
    }
}

// ---------------------------------------------------------------------------
// 6) Attention: one block per (sequence, head). S = T = 14, head dim 48.
//    Q/K/V read with per-tensor leading dim; O written [M,384] at col h*48.
// ---------------------------------------------------------------------------
__global__ void attn_kernel(const float* __restrict__ Q, int ldq,
                            const float* __restrict__ K, int ldk,
                            const float* __restrict__ V, int ldv,
                            float* __restrict__ O)
{
    int s = blockIdx.x;
    int h = blockIdx.y;
    __shared__ float qs[HTOK][HDIM + 1];
    __shared__ float ks[HTOK][HDIM + 1];
    __shared__ float vs[HTOK][HDIM + 1];
    __shared__ float a [HTOK][HTOK + 1];
    int tid = threadIdx.x;

    for (int i = tid; i < HTOK * HDIM; i += blockDim.x) {
        int r = i / HDIM, c = i % HDIM;
        size_t base = (size_t)(s * HTOK + r);
        qs[r][c] = Q[base * ldq + h * HDIM + c];
        ks[r][c] = K[base * ldk + h * HDIM + c];
        vs[r][c] = V[base * ldv + h * HDIM + c];
    }
    __syncthreads();

    const float scale = 0.14433756729740645f;   // 1/sqrt(48)
    for (int i = tid; i < HTOK * HTOK; i += blockDim.x) {
        int qi = i / HTOK, kj = i % HTOK;
        float p = 0.f;
        #pragma unroll
        for (int e = 0; e < HDIM; ++e) p += qs[qi][e] * ks[kj][e];
        a[qi][kj] = p * scale;
    }
    __syncthreads();

    if (tid < HTOK) {
        float mx = -INFINITY;
        #pragma unroll
        for (int j = 0; j < HTOK; ++j) mx = fmaxf(mx, a[tid][j]);
        float sum = 0.f;
        #pragma unroll
        for (int j = 0; j < HTOK; ++j) { float e = expf(a[tid][j] - mx); a[tid][j] = e; sum += e; }
        float inv = 1.f / sum;
        #pragma unroll
        for (int j = 0; j < HTOK; ++j) a[tid][j] *= inv;
    }
    __syncthreads();

    for (int i = tid; i < HTOK * HDIM; i += blockDim.x) {
        int r = i / HDIM, e = i % HDIM;
        float p = 0.f;
        #pragma unroll
        for (int j = 0; j < HTOK; ++j) p += a[r][j] * vs[j][e];
        O[(size_t)(s * HTOK + r) * Dm + h * HDIM + e] = p;
    }
}

// ---------------------------------------------------------------------------
// Host launcher — graph-capturable: kernel launches on the default stream only.
// ---------------------------------------------------------------------------
extern "C" void kernel_launch(void* const* d_in, const int* in_sizes, int n_in,
                              void* d_out, int out_size)
{
    const float* qt    = (const float*)d_in[0];   // (64,1,14,384)  == (64,14,384)
    const float* nd    = (const float*)d_in[1];   // (64,8192,1,384) == (64,8192,384)
    const float* sa_w  = (const float*)d_in[2];
    const float* sa_b  = (const float*)d_in[3];
    const float* sa_ow = (const float*)d_in[4];
    const float* sa_ob = (const float*)d_in[5];
    const float* ca_w  = (const float*)d_in[6];
    const float* ca_b  = (const float*)d_in[7];
    const float* ca_ow = (const float*)d_in[8];
    const float* ca_ob = (const float*)d_in[9];
    const float* ln1w  = (const float*)d_in[10];
    const float* ln1b  = (const float*)d_in[11];
    const float* ln2w  = (const float*)d_in[12];
    const float* ln2b  = (const float*)d_in[13];
    const float* ln3w  = (const float*)d_in[14];
    const float* ln3b  = (const float*)d_in[15];
    const float* f1w   = (const float*)d_in[16];
    const float* f1b   = (const float*)d_in[17];
    const float* f2w   = (const float*)d_in[18];
    const float* f2b   = (const float*)d_in[19];
    const float* fnw   = (const float*)d_in[20];
    const float* fnb   = (const float*)d_in[21];

    float *sim, *x, *mem, *h, *q, *o, *qkv, *kv, *ff;
    int* idx;
    cudaGetSymbolAddress((void**)&sim, g_sim);
    cudaGetSymbolAddress((void**)&idx, g_idx);
    cudaGetSymbolAddress((void**)&x,   g_x);
    cudaGetSymbolAddress((void**)&mem, g_mem);
    cudaGetSymbolAddress((void**)&h,   g_h);
    cudaGetSymbolAddress((void**)&q,   g_q);
    cudaGetSymbolAddress((void**)&o,   g_o);
    cudaGetSymbolAddress((void**)&qkv, g_qkv);
    cudaGetSymbolAddress((void**)&kv,  g_kv);
    cudaGetSymbolAddress((void**)&ff,  g_ff);

    // --- retrieval ---
    sim_kernel<<<dim3(NNODES / 256, BATCH), 256>>>(qt, nd, sim);
    topk_kernel<<<BATCH * HTOK, 256>>>(sim, idx);
    gather_kernel<<<MTOK, 128>>>(qt, nd, idx, x, mem);

    const dim3 gN384 (Dm / 64,        MTOK / 64);  // (6,140)
    const dim3 gN768 (2 * Dm / 64,    MTOK / 64);  // (12,140)
    const dim3 gN1152(3 * Dm / 64,    MTOK / 64);  // (18,140)
    const dim3 gN1536(4 * Dm / 64,    MTOK / 64);  // (24,140)

    for (int i = 0; i < NLAYER; ++i) {
        const float* SAW = sa_w  + (size_t)i * 3 * Dm * Dm;
        const float* SAB = sa_b  + (size_t)i * 3 * Dm;
        const float* SOW = sa_ow + (size_t)i * Dm * Dm;
        const float* SOB = sa_ob + (size_t)i * Dm;
        const float* CAW = ca_w  + (size_t)i * 3 * Dm * Dm;
        const float* CAB = ca_b  + (size_t)i * 3 * Dm;
        const float* COW = ca_ow + (size_t)i * Dm * Dm;
        const float* COB = ca_ob + (size_t)i * Dm;
        const float* F1W = f1w   + (size_t)i * 4 * Dm * Dm;
        const float* F1B = f1b   + (size_t)i * 4 * Dm;
        const float* F2W = f2w   + (size_t)i * 4 * Dm * Dm;
        const float* F2B = f2b   + (size_t)i * Dm;

        // self-attention
        ln_kernel<<<MTOK / 8, 256>>>(x, h, nullptr, ln1w + i * Dm, ln1b + i * Dm);
        gemm_kernel<0><<<gN1152, 256>>>(h, SAW, SAB, qkv, MTOK, 3 * Dm, Dm);
        attn_kernel<<<dim3(MTOK / HTOK, NHEAD), 128>>>(qkv, 3 * Dm,
                                                       qkv + Dm, 3 * Dm,
                                                       qkv + 2 * Dm, 3 * Dm, o);
        gemm_kernel<2><<<gN384, 256>>>(o, SOW, SOB, x, MTOK, Dm, Dm);

        // cross-attention (memory is NOT layer-normed, matches reference)
        ln_kernel<<<MTOK / 8, 256>>>(x, h, nullptr, ln2w + i * Dm, ln2b + i * Dm);
        gemm_kernel<0><<<gN384, 256>>>(h, CAW, CAB, q, MTOK, Dm, Dm);
        gemm_kernel<0><<<gN768, 256>>>(mem, CAW + Dm * Dm, CAB + Dm, kv, MTOK, 2 * Dm, Dm);
        attn_kernel<<<dim3(MTOK / HTOK, NHEAD), 128>>>(q, Dm,
                                                       kv, 2 * Dm,
                                                       kv + Dm, 2 * Dm, o);
        gemm_kernel<2><<<gN384, 256>>>(o, COW, COB, x, MTOK, Dm, Dm);

        // FFN
        ln_kernel<<<MTOK / 8, 256>>>(x, h, nullptr, ln3w + i * Dm, ln3b + i * Dm);
        gemm_kernel<1><<<gN1536, 256>>>(h, F1W, F1B, ff, MTOK, 4 * Dm, Dm);
        gemm_kernel<2><<<gN384, 256>>>(ff, F2W, F2B, x, MTOK, Dm, 4 * Dm);

        // after block 2: x = LN(x, fn[0]); mem2 = x (fixed for blocks 3..5)
        if (i == 2)
            ln_kernel<<<MTOK / 8, 256>>>(x, x, mem, fnw, fnb);
    }

    // final norm -> output (64,10,14,384) row order matches x row order
    ln_kernel<<<MTOK / 8, 256>>>(x, (float*)d_out, nullptr, fnw + Dm, fnb + Dm);
}

// round 14
// speedup vs baseline: 1.9853x; 1.9853x over previous
#include <cuda_runtime.h>
#include <cuda_bf16.h>
#include <math.h>
#include <stdint.h>

// ---------------------------------------------------------------------------
// Problem constants
// ---------------------------------------------------------------------------
#define Dm      384
#define NHEAD   8
#define HDIM    48
#define KNN     10
#define NLAYER  6
#define BATCH   64
#define HTOK    14
#define NNODES  8192
#define MTOK    8960          // 640 * 14
#define EPSLN   1e-5f

// Weight block element counts (all 6 layers concatenated)
#define NW_SAW  (NLAYER * 3 * Dm * Dm)
#define NW_SOW  (NLAYER * Dm * Dm)
#define NW_F1   (NLAYER * 4 * Dm * Dm)
#define OFF_SAW 0
#define OFF_SOW (NW_SAW)
#define OFF_CAW (NW_SAW + NW_SOW)
#define OFF_COW (OFF_CAW + NW_SAW)
#define OFF_F1  (OFF_COW + NW_SOW)
#define OFF_F2  (OFF_F1 + NW_F1)
#define NW_TOT  (OFF_F2 + NW_F1)

// ---------------------------------------------------------------------------
// Device scratch (allocation-free)
// ---------------------------------------------------------------------------
__device__ __align__(16) float          g_sim [BATCH * HTOK * NNODES];
__device__ __align__(16) int            g_idx [BATCH * HTOK * KNN];
__device__ __align__(16) float          g_x   [MTOK * Dm];
__device__ __align__(16) float          g_q   [MTOK * Dm];
__device__ __align__(16) float          g_qkv [MTOK * 3 * Dm];
__device__ __align__(16) float          g_kv  [MTOK * 2 * Dm];
__device__ __align__(16) __nv_bfloat16  g_hhi [MTOK * Dm];
__device__ __align__(16) __nv_bfloat16  g_hlo [MTOK * Dm];
__device__ __align__(16) __nv_bfloat16  g_mhi [MTOK * Dm];
__device__ __align__(16) __nv_bfloat16  g_mlo [MTOK * Dm];
__device__ __align__(16) __nv_bfloat16  g_ohi [MTOK * Dm];
__device__ __align__(16) __nv_bfloat16  g_olo [MTOK * Dm];
__device__ __align__(16) __nv_bfloat16  g_fhi [MTOK * 4 * Dm];
__device__ __align__(16) __nv_bfloat16  g_flo [MTOK * 4 * Dm];
__device__ __align__(16) __nv_bfloat16  g_whi [NW_TOT];
__device__ __align__(16) __nv_bfloat16  g_wlo [NW_TOT];

// ---------------------------------------------------------------------------
// Baseline-PTX helpers (no "a"-gated features: mma.sync / ldmatrix / cp.async)
// ---------------------------------------------------------------------------
__device__ __forceinline__ uint32_t smem_to_u32(const void* p) {
    uint32_t a;
    asm("{ .reg .u64 t; cvta.to.shared.u64 t, %1; cvt.u32.u64 %0, t; }"
        : "=r"(a) : "l"(p));
    return a;
}

#define CP16(dst, src) \
    asm volatile("cp.async.ca.shared.global [%0], [%1], 16;" \
                 :: "r"(dst), "l"(src))
#define CP_COMMIT() asm volatile("cp.async.commit_group;")

#define LDSM4(r, addr) \
    asm volatile("ldmatrix.sync.aligned.m8n8.x4.shared.b16 {%0,%1,%2,%3}, [%4];" \
                 : "=r"((r)[0]), "=r"((r)[1]), "=r"((r)[2]), "=r"((r)[3]) \
                 : "r"(addr))

#define MMA16816(c, a, b0, b1) \
    asm volatile("mma.sync.aligned.m16n8k16.row.col.f32.bf16.bf16.f32 " \
                 "{%0,%1,%2,%3},{%4,%5,%6,%7},{%8,%9},{%0,%1,%2,%3};" \
                 : "+f"((c)[0]), "+f"((c)[1]), "+f"((c)[2]), "+f"((c)[3]) \
                 : "r"((a)[0]), "r"((a)[1]), "r"((a)[2]), "r"((a)[3]), \
                   "r"(b0), "r"(b1))

// ---------------------------------------------------------------------------
// fp32 -> bf16 hi/lo split
// ---------------------------------------------------------------------------
__device__ __forceinline__ void split_bf16(float v, __nv_bfloat16& hi, __nv_bfloat16& lo)
{
    hi = __float2bfloat16(v);
    lo = __float2bfloat16(v - __bfloat162float(hi));
}

// ---------------------------------------------------------------------------
// Weight conversion: fp32 -> bf16 hi/lo
// ---------------------------------------------------------------------------
__global__ void wconv_kernel(const float* __restrict__ src,
                             __nv_bfloat16* __restrict__ hi,
                             __nv_bfloat16* __restrict__ lo, int n)
{
    for (int i = blockIdx.x * blockDim.x + threadIdx.x; i < n;
         i += gridDim.x * blockDim.x) {
        __nv_bfloat16 h, l;
        split_bf16(src[i], h, l);
        hi[i] = h; lo[i] = l;
    }
}

// ---------------------------------------------------------------------------
// sim[b,h,n] = dot(qt[b,h,:], nd[b,n,:])
// ---------------------------------------------------------------------------
__global__ void sim_kernel(const float* __restrict__ qt,
                           const float* __restrict__ nd,
                           float* __restrict__ sim)
{
    int b = blockIdx.y;
    __shared__ float qts[HTOK * Dm];
    for (int i = threadIdx.x; i < HTOK * Dm; i += blockDim.x)
        qts[i] = qt[(size_t)b * HTOK * Dm + i];
    __syncthreads();

    int warp = threadIdx.x >> 5, lane = threadIdx.x & 31;
    int node0 = blockIdx.x * 256 + warp * 32;

    for (int it = 0; it < 32; ++it) {
        int node = node0 + it;
        const float* row = nd + ((size_t)b * NNODES + node) * Dm;
        float v[12];
        #pragma unroll
        for (int j = 0; j < 12; ++j) v[j] = row[lane + 32 * j];
        #pragma unroll
        for (int h = 0; h < HTOK; ++h) {
            float p = 0.f;
            #pragma unroll
            for (int j = 0; j < 12; ++j) p += v[j] * qts[h * Dm + lane + 32 * j];
            #pragma unroll
            for (int o = 16; o > 0; o >>= 1) p += __shfl_xor_sync(0xffffffffu, p, o);
            if (lane == 0)
                sim[((size_t)(b * HTOK + h)) * NNODES + node] = p;
        }
    }
}

// ---------------------------------------------------------------------------
// top-10 per row, descending, ties -> lowest index
// ---------------------------------------------------------------------------
__global__ void topk_kernel(const float* __restrict__ sim, int* __restrict__ idx)
{
    __shared__ float vals[NNODES];
    __shared__ float rv[256];
    __shared__ int   ri[256];
    int row = blockIdx.x;
    const float* s = sim + (size_t)row * NNODES;
    for (int i = threadIdx.x; i < NNODES; i += 256) vals[i] = s[i];
    __syncthreads();

    for (int t = 0; t < KNN; ++t) {
        float bv = -INFINITY; int bi = 0;
        for (int i = threadIdx.x; i < NNODES; i += 256) {
            float v = vals[i];
            if (v > bv) { bv = v; bi = i; }
        }
        rv[threadIdx.x] = bv; ri[threadIdx.x] = bi;
        __syncthreads();
        for (int s2 = 128; s2 > 0; s2 >>= 1) {
            if (threadIdx.x < s2) {
                float ov = rv[threadIdx.x + s2]; int oi = ri[threadIdx.x + s2];
                if (ov > rv[threadIdx.x] ||
                    (ov == rv[threadIdx.x] && oi < ri[threadIdx.x])) {
                    rv[threadIdx.x] = ov; ri[threadIdx.x] = oi;
                }
            }
            __syncthreads();
        }
        if (threadIdx.x == 0) { idx[row * KNN + t] = ri[0]; vals[ri[0]] = -INFINITY; }
        __syncthreads();
    }
}

// ---------------------------------------------------------------------------
// gather: x fp32 (broadcast qt) ; mem -> bf16 hi/lo (gathered nodes)
// ---------------------------------------------------------------------------
__global__ void gather_kernel(const float* __restrict__ qt,
                              const float* __restrict__ nd,
                              const int*   __restrict__ idx,
                              float* __restrict__ x,
                              __nv_bfloat16* __restrict__ mhi,
                              __nv_bfloat16* __restrict__ mlo)
{
    int row = blockIdx.x;
    int b = row / (KNN * HTOK);
    int k = (row / HTOK) % KNN;
    int h = row % HTOK;
    const float* sx = qt + (size_t)(b * HTOK + h) * Dm;
    int node = idx[(b * HTOK + h) * KNN + k];
    const float* sm = nd + ((size_t)b * NNODES + node) * Dm;
    for (int e = threadIdx.x; e < Dm; e += blockDim.x) {
        x[(size_t)row * Dm + e] = sx[e];
        __nv_bfloat16 hi, lo;
        split_bf16(sm[e], hi, lo);
        mhi[(size_t)row * Dm + e] = hi;
        mlo[(size_t)row * Dm + e] = lo;
    }
}

// ---------------------------------------------------------------------------
// LayerNorm: warp per row; outputs fp32 (optional) and bf16 hi/lo (optional)
// ---------------------------------------------------------------------------
__global__ void ln_kernel(const float* __restrict__ in,
                          const float* __restrict__ w, const float* __restrict__ bias,
                          float* __restrict__ outf,
                          __nv_bfloat16* __restrict__ ohi,
                          __nv_bfloat16* __restrict__ olo)
{
    int warp = threadIdx.x >> 5, lane = threadIdx.x & 31;
    int row = blockIdx.x * (blockDim.x >> 5) + warp;
    if (row >= MTOK) return;
    const float* p = in + (size_t)row * Dm;
    float v[12];
    float s = 0.f;
    #pragma unroll
    for (int j = 0; j < 12; ++j) { v[j] = p[lane + 32 * j]; s += v[j]; }
    #pragma unroll
    for (int o = 16; o > 0; o >>= 1) s += __shfl_xor_sync(0xffffffffu, s, o);
    float mu = s * (1.f / Dm);
    float q = 0.f;
    #pragma unroll
    for (int j = 0; j < 12; ++j) { float d = v[j] - mu; q += d * d; }
    #pragma unroll
    for (int o = 16; o > 0; o >>= 1) q += __shfl_xor_sync(0xffffffffu, q, o);
    float inv = rsqrtf(q * (1.f / Dm) + EPSLN);
    #pragma unroll
    for (int j = 0; j < 12; ++j) {
        int c = lane + 32 * j;
        float r = (v[j] - mu) * inv * w[c] + bias[c];
        if (outf) outf[(size_t)row * Dm + c] = r;
        if (ohi) {
            __nv_bfloat16 hi, lo;
            split_bf16(r, hi, lo);
            ohi[(size_t)row * Dm + c] = hi;
            olo[(size_t)row * Dm + c] = lo;
        }
    }
}

// ---------------------------------------------------------------------------
// Attention: one block per (sequence, head). S=T=14, head dim 48.
// Inputs fp32; output bf16 hi/lo [M,384].
// ---------------------------------------------------------------------------
__global__ void attn_kernel(const float* __restrict__ Q, int ldq,
                            const float* __restrict__ K, int ldk,
                            const float* __restrict__ V, int ldv,
                            __nv_bfloat16* __restrict__ Ohi,
                            __nv_bfloat16* __restrict__ Olo)
{
    int s = blockIdx.x;
    int h = blockIdx.y;
    __shared__ float qs[HTOK][HDIM + 1];
    __shared__ float ks[HTOK][HDIM + 1];
    __shared__ float vs[HTOK][HDIM + 1];
    __shared__ float a [HTOK][HTOK + 1];
    int tid = threadIdx.x;

    for (int i = tid; i < HTOK * HDIM; i += blockDim.x) {
        int r = i / HDIM, c = i % HDIM;
        size_t base = (size_t)(s * HTOK + r);
        qs[r][c] = Q[base * ldq + h * HDIM + c];
        ks[r][c] = K[base * ldk + h * HDIM + c];
        vs[r][c] = V[base * ldv + h * HDIM + c];
    }
    __syncthreads();

    const float scale = 0.14433756729740645f;   // 1/sqrt(48)
    for (int i = tid; i < HTOK * HTOK; i += blockDim.x) {
        int qi = i / HTOK, kj = i % HTOK;
        float p = 0.f;
        #pragma unroll
        for (int e = 0; e < HDIM; ++e) p += qs[qi][e] * ks[kj][e];
        a[qi][kj] = p * scale;
    }
    __syncthreads();

    if (tid < HTOK) {
        float mx = -INFINITY;
        #pragma unroll
        for (int j = 0; j < HTOK; ++j) mx = fmaxf(mx, a[tid][j]);
        float sum = 0.f;
        #pragma unroll
        for (int j = 0; j < HTOK; ++j) { float e = expf(a[tid][j] - mx); a[tid][j] = e; sum += e; }
        float inv = 1.f / sum;
        #pragma unroll
        for (int j = 0; j < HTOK; ++j) a[tid][j] *= inv;
    }
    __syncthreads();

    for (int i = tid; i < HTOK * HDIM; i += blockDim.x) {
        int r = i / HDIM, e = i % HDIM;
        float p = 0.f;
        #pragma unroll
        for (int j = 0; j < HTOK; ++j) p += a[r][j] * vs[j][e];
        size_t oidx = (size_t)(s * HTOK + r) * Dm + h * HDIM + e;
        __nv_bfloat16 hi, lo;
        split_bf16(p, hi, lo);
        Ohi[oidx] = hi;
        Olo[oidx] = lo;
    }
}

// ---------------------------------------------------------------------------
// HMMA GEMM (mma.sync m16n8k16 bf16, fp32 acc), split-3:
//   C[m,n] = sum_k (Ahi+Alo)[m,k]*(Bhi+Blo)[n,k] + bias[n]   (drop Alo*Blo)
//   CTA tile 128x128, BK=32, 256 threads (8 warps, warp tile 64x32).
//   cp.async double-buffered smem; rows padded to 40 bf16 (ldmatrix
//   conflict-free: 80B stride -> distinct 16B banks mod 128 across 8 rows).
//   EPI: 0 = fp32 store; 1 = gelu -> bf16 hi/lo; 2 = residual add fp32
// ---------------------------------------------------------------------------
__device__ __forceinline__ float gelu_exact(float x)
{
    return 0.5f * x * (1.0f + erff(x * 0.70710678118654752f));
}

#define BM   128
#define BN   128
#define BK   32
#define SST  40                         // smem row stride in bf16
#define TILEB   (BM * SST * 2)          // bytes per tile  = 10240
#define STAGEB  (4 * TILEB)             // Ahi,Alo,Bhi,Blo = 40960
#define S_TOTAL (2 * STAGEB)            // double buffered  = 81920

template <int EPI>
__global__ void __launch_bounds__(256, 1)
gemm_mma(const __nv_bfloat16* __restrict__ Ahi, const __nv_bfloat16* __restrict__ Alo,
         const __nv_bfloat16* __restrict__ Bhi, const __nv_bfloat16* __restrict__ Blo,
         const float* __restrict__ bias,
         float* __restrict__ C,
         __nv_bfloat16* __restrict__ Chi, __nv_bfloat16* __restrict__ Clo,
         int M, int N, int K)
{
    extern __shared__ __nv_bfloat16 smb[];
    const int tid  = threadIdx.x;
    const int wid  = tid >> 5, lane = tid & 31;
    const int wm   = wid & 1;          // 2 warps over M (64 each)
    const int wn   = wid >> 1;         // 4 warps over N (32 each)
    const int m0   = blockIdx.y * BM;
    const int n0   = blockIdx.x * BN;
    const uint32_t sb = smem_to_u32(smb);

    float acc[4][4][4];
    #pragma unroll
    for (int i = 0; i < 4; ++i)
        #pragma unroll
        for (int j = 0; j < 4; ++j)
            #pragma unroll
            for (int r = 0; r < 4; ++r) acc[i][j][r] = 0.f;

    const int nch = K >> 5;

    auto issue = [&](int stg, int k0) {
        uint32_t base = sb + (uint32_t)stg * STAGEB;
        #pragma unroll
        for (int i = 0; i < 2; ++i) {
            int v   = tid + 256 * i;        // 0..511
            int row = v >> 2, seg = v & 3;  // 128 rows x 4 16B-segments
            uint32_t doff = (uint32_t)(row * SST + seg * 8) * 2;
            size_t go = (size_t)row * K + k0 + seg * 8;
            CP16(base + 0 * TILEB + doff, Ahi + (size_t)m0 * K + go);
            CP16(base + 1 * TILEB + doff, Alo + (size_t)m0 * K + go);
            CP16(base + 2 * TILEB + doff, Bhi + (size_t)n0 * K + go);
            CP16(base + 3 * TILEB + doff, Blo + (size_t)n0 * K + go);
        }
        CP_COMMIT();
    };

    issue(0, 0);

    for (int c = 0; c < nch; ++c) {
        if (c + 1 < nch) {
            issue((c + 1) & 1, (c + 1) * BK);
            asm volatile("cp.async.wait_group 1;");
        } else {
            asm volatile("cp.async.wait_group 0;");
        }
        __syncthreads();

        uint32_t base = sb + (uint32_t)(c & 1) * STAGEB;

        #pragma unroll
        for (int kk = 0; kk < BK; kk += 16) {
            uint32_t ahi[4][4], alo[4][4], bhi[2][4], blo[2][4];

            // A fragments: 16x16 row-major per mtile
            int arow = wm * 64 + (lane & 15);
            int acol = kk + ((lane >> 4) << 3);
            #pragma unroll
            for (int mt = 0; mt < 4; ++mt) {
                uint32_t ad = base + (uint32_t)((arow + mt * 16) * SST + acol) * 2;
                LDSM4(ahi[mt], ad + 0 * TILEB);
                LDSM4(alo[mt], ad + 1 * TILEB);
            }

            // B fragments: two n8-tiles per x4 (regs: [b0 n0, b1 n0, b0 n1, b1 n1])
            int brow = wn * 32 + (lane & 7) + ((lane & 16) ? 8 : 0);
            int bcol = kk + ((lane & 8) ? 8 : 0);
            #pragma unroll
            for (int np = 0; np < 2; ++np) {
                uint32_t bd = base + (uint32_t)((brow + np * 16) * SST + bcol) * 2;
                LDSM4(bhi[np], bd + 2 * TILEB);
                LDSM4(blo[np], bd + 3 * TILEB);
            }

            #pragma unroll
            for (int mt = 0; mt < 4; ++mt)
                #pragma unroll
                for (int nt = 0; nt < 4; ++nt) {
                    int np = nt >> 1, hh = (nt & 1) << 1;
                    MMA16816(acc[mt][nt], ahi[mt], bhi[np][hh], bhi[np][hh + 1]);
                    MMA16816(acc[mt][nt], ahi[mt], blo[np][hh], blo[np][hh + 1]);
                    MMA16816(acc[mt][nt], alo[mt], bhi[np][hh], bhi[np][hh + 1]);
                }
        }
        __syncthreads();
    }

    // ---- epilogue ----
    #pragma unroll
    for (int mt = 0; mt < 4; ++mt) {
        #pragma unroll
        for (int nt = 0; nt < 4; ++nt) {
            int row0 = m0 + wm * 64 + mt * 16 + (lane >> 2);
            int col  = n0 + wn * 32 + nt * 8 + ((lane & 3) << 1);
            float b0v = bias[col], b1v = bias[col + 1];
            float v00 = acc[mt][nt][0] + b0v, v01 = acc[mt][nt][1] + b1v;
            float v10 = acc[mt][nt][2] + b0v, v11 = acc[mt][nt][3] + b1v;
            if (EPI == 1) {
                v00 = gelu_exact(v00); v01 = gelu_exact(v01);
                v10 = gelu_exact(v10); v11 = gelu_exact(v11);
                __nv_bfloat16 h0, l0, h1, l1;
                split_bf16(v00, h0, l0); split_bf16(v01, h1, l1);
                *(__nv_bfloat162*)(Chi + (size_t)row0 * N + col) = __halves2bfloat162(h0, h1);
                *(__nv_bfloat162*)(Clo + (size_t)row0 * N + col) = __halves2bfloat162(l0, l1);
                split_bf16(v10, h0, l0); split_bf16(v11, h1, l1);
                *(__nv_bfloat162*)(Chi + (size_t)(row0 + 8) * N + col) = __halves2bfloat162(h0, h1);
                *(__nv_bfloat162*)(Clo + (size_t)(row0 + 8) * N + col) = __halves2bfloat162(l0, l1);
            } else {
                float2* p0 = (float2*)(C + (size_t)row0 * N + col);
                float2* p1 = (float2*)(C + (size_t)(row0 + 8) * N + col);
                if (EPI == 2) {
                    float2 o0 = *p0, o1 = *p1;
                    v00 += o0.x; v01 += o0.y; v10 += o1.x; v11 += o1.y;
                }
                *p0 = make_float2(v00, v01);
                *p1 = make_float2(v10, v11);
            }
        }
    }
}

// ---------------------------------------------------------------------------
// Host launcher — graph-capturable (kernel launches only, default stream)
// ---------------------------------------------------------------------------
extern "C" void kernel_launch(void* const* d_in, const int* in_sizes, int n_in,
                              void* d_out, int out_size)
{
    const float* qt    = (const float*)d_in[0];
    const float* nd    = (const float*)d_in[1];
    const float* sa_w  = (const float*)d_in[2];
    const float* sa_b  = (const float*)d_in[3];
    const float* sa_ow = (const float*)d_in[4];
    const float* sa_ob = (const float*)d_in[5];
    const float* ca_w  = (const float*)d_in[6];
    const float* ca_b  = (const float*)d_in[7];
    const float* ca_ow = (const float*)d_in[8];
    const float* ca_ob = (const float*)d_in[9];
    const float* ln1w  = (const float*)d_in[10];
    const float* ln1b  = (const float*)d_in[11];
    const float* ln2w  = (const float*)d_in[12];
    const float* ln2b  = (const float*)d_in[13];
    const float* ln3w  = (const float*)d_in[14];
    const float* ln3b  = (const float*)d_in[15];
    const float* f1w   = (const float*)d_in[16];
    const float* f1b   = (const float*)d_in[17];
    const float* f2w   = (const float*)d_in[18];
    const float* f2b   = (const float*)d_in[19];
    const float* fnw   = (const float*)d_in[20];
    const float* fnb   = (const float*)d_in[21];

    float *sim, *x, *q, *qkv, *kv;
    int* idx;
    __nv_bfloat16 *hhi, *hlo, *mhi, *mlo, *ohi, *olo, *fhi, *flo, *whi, *wlo;
    cudaGetSymbolAddress((void**)&sim, g_sim);
    cudaGetSymbolAddress((void**)&idx, g_idx);
    cudaGetSymbolAddress((void**)&x,   g_x);
    cudaGetSymbolAddress((void**)&q,   g_q);
    cudaGetSymbolAddress((void**)&qkv, g_qkv);
    cudaGetSymbolAddress((void**)&kv,  g_kv);
    cudaGetSymbolAddress((void**)&hhi, g_hhi);
    cudaGetSymbolAddress((void**)&hlo, g_hlo);
    cudaGetSymbolAddress((void**)&mhi, g_mhi);
    cudaGetSymbolAddress((void**)&mlo, g_mlo);
    cudaGetSymbolAddress((void**)&ohi, g_ohi);
    cudaGetSymbolAddress((void**)&olo, g_olo);
    cudaGetSymbolAddress((void**)&fhi, g_fhi);
    cudaGetSymbolAddress((void**)&flo, g_flo);
    cudaGetSymbolAddress((void**)&whi, g_whi);
    cudaGetSymbolAddress((void**)&wlo, g_wlo);

    cudaFuncSetAttribute(gemm_mma<0>, cudaFuncAttributeMaxDynamicSharedMemorySize, S_TOTAL);
    cudaFuncSetAttribute(gemm_mma<1>, cudaFuncAttributeMaxDynamicSharedMemorySize, S_TOTAL);
    cudaFuncSetAttribute(gemm_mma<2>, cudaFuncAttributeMaxDynamicSharedMemorySize, S_TOTAL);

    // --- weight conversion (fp32 -> bf16 hi/lo) ---
    wconv_kernel<<<1024, 256>>>(sa_w,  whi + OFF_SAW, wlo + OFF_SAW, NW_SAW);
    wconv_kernel<<<1024, 256>>>(sa_ow, whi + OFF_SOW, wlo + OFF_SOW, NW_SOW);
    wconv_kernel<<<1024, 256>>>(ca_w,  whi + OFF_CAW, wlo + OFF_CAW, NW_SAW);
    wconv_kernel<<<1024, 256>>>(ca_ow, whi + OFF_COW, wlo + OFF_COW, NW_SOW);
    wconv_kernel<<<1024, 256>>>(f1w,   whi + OFF_F1,  wlo + OFF_F1,  NW_F1);
    wconv_kernel<<<1024, 256>>>(f2w,   whi + OFF_F2,  wlo + OFF_F2,  NW_F1);

    // --- retrieval ---
    sim_kernel<<<dim3(NNODES / 256, BATCH), 256>>>(qt, nd, sim);
    topk_kernel<<<BATCH * HTOK, 256>>>(sim, idx);
    gather_kernel<<<MTOK, 128>>>(qt, nd, idx, x, mhi, mlo);

    const dim3 blk(256);
    const dim3 gN384 (3,  MTOK / BM);
    const dim3 gN768 (6,  MTOK / BM);
    const dim3 gN1152(9,  MTOK / BM);
    const dim3 gN1536(12, MTOK / BM);

    for (int i = 0; i < NLAYER; ++i) {
        const __nv_bfloat16* SAWh = whi + OFF_SAW + (size_t)i * 3 * Dm * Dm;
        const __nv_bfloat16* SAWl = wlo + OFF_SAW + (size_t)i * 3 * Dm * Dm;
        const __nv_bfloat16* SOWh = whi + OFF_SOW + (size_t)i * Dm * Dm;
        const __nv_bfloat16* SOWl = wlo + OFF_SOW + (size_t)i * Dm * Dm;
        const __nv_bfloat16* CAWh = whi + OFF_CAW + (size_t)i * 3 * Dm * Dm;
        const __nv_bfloat16* CAWl = wlo + OFF_CAW + (size_t)i * 3 * Dm * Dm;
        const __nv_bfloat16* COWh = whi + OFF_COW + (size_t)i * Dm * Dm;
        const __nv_bfloat16* COWl = wlo + OFF_COW + (size_t)i * Dm * Dm;
        const __nv_bfloat16* F1h  = whi + OFF_F1  + (size_t)i * 4 * Dm * Dm;
        const __nv_bfloat16* F1l  = wlo + OFF_F1  + (size_t)i * 4 * Dm * Dm;
        const __nv_bfloat16* F2h  = whi + OFF_F2  + (size_t)i * 4 * Dm * Dm;
        const __nv_bfloat16* F2l  = wlo + OFF_F2  + (size_t)i * 4 * Dm * Dm;
        const float* SAB = sa_b  + (size_t)i * 3 * Dm;
        const float* SOB = sa_ob + (size_t)i * Dm;
        const float* CAB = ca_b  + (size_t)i * 3 * Dm;
        const float* COB = ca_ob + (size_t)i * Dm;
        const float* F1B = f1b   + (size_t)i * 4 * Dm;
        const float* F2B = f2b   + (size_t)i * Dm;

        // self-attention
        ln_kernel<<<MTOK / 8, 256>>>(x, ln1w + i * Dm, ln1b + i * Dm, nullptr, hhi, hlo);
        gemm_mma<0><<<gN1152, blk, S_TOTAL>>>(hhi, hlo, SAWh, SAWl, SAB, qkv,
                                              nullptr, nullptr, MTOK, 3 * Dm, Dm);
        attn_kernel<<<dim3(MTOK / HTOK, NHEAD), 128>>>(qkv, 3 * Dm,
                                                       qkv + Dm, 3 * Dm,
                                                       qkv + 2 * Dm, 3 * Dm, ohi, olo);
        gemm_mma<2><<<gN384, blk, S_TOTAL>>>(ohi, olo, SOWh, SOWl, SOB, x,
                                             nullptr, nullptr, MTOK, Dm, Dm);

        // cross-attention (memory not layer-normed, per reference)
        ln_kernel<<<MTOK / 8, 256>>>(x, ln2w + i * Dm, ln2b + i * Dm, nullptr, hhi, hlo);
        gemm_mma<0><<<gN384, blk, S_TOTAL>>>(hhi, hlo, CAWh, CAWl, CAB, q,
                                             nullptr, nullptr, MTOK, Dm, Dm);
        gemm_mma<0><<<gN768, blk, S_TOTAL>>>(mhi, mlo,
                                             CAWh + (size_t)Dm * Dm, CAWl + (size_t)Dm * Dm,
                                             CAB + Dm, kv,
                                             nullptr, nullptr, MTOK, 2 * Dm, Dm);
        attn_kernel<<<dim3(MTOK / HTOK, NHEAD), 128>>>(q, Dm,
                                                       kv, 2 * Dm,
                                                       kv + Dm, 2 * Dm, ohi, olo);
        gemm_mma<2><<<gN384, blk, S_TOTAL>>>(ohi, olo, COWh, COWl, COB, x,
                                             nullptr, nullptr, MTOK, Dm, Dm);

        // FFN
        ln_kernel<<<MTOK / 8, 256>>>(x, ln3w + i * Dm, ln3b + i * Dm, nullptr, hhi, hlo);
        gemm_mma<1><<<gN1536, blk, S_TOTAL>>>(hhi, hlo, F1h, F1l, F1B, nullptr,
                                              fhi, flo, MTOK, 4 * Dm, Dm);
        gemm_mma<2><<<gN384, blk, S_TOTAL>>>(fhi, flo, F2h, F2l, F2B, x,
                                             nullptr, nullptr, MTOK, Dm, 4 * Dm);

        // after block 2: x = LN(x, fn[0]); mem2 = normed x (bf16 hi/lo)
        if (i == 2)
            ln_kernel<<<MTOK / 8, 256>>>(x, fnw, fnb, x, mhi, mlo);
    }

    // final norm -> fp32 output
    ln_kernel<<<MTOK / 8, 256>>>(x, fnw + Dm, fnb + Dm, (float*)d_out, nullptr, nullptr);
}